// round 1
// baseline (speedup 1.0000x reference)
#include <cuda_runtime.h>

// ---------------------------------------------------------------------------
// MaskedBalancedBCELoss (DBNet-style) on GB300.
//
// result = (positive_sum + topk_negative_sum) / (pos_count + neg_count + eps)
//   neg_count = pos_count==0 ? 0 : min(neg_total, 3*pos_count)
//
// Selection trick: negative loss -log1p(-p) is strictly increasing in p, so
// the top-k negative losses are exactly the k negatives with the largest pred.
// We therefore select on a histogram of p (uniform -> well conditioned):
//   K1: coarse 32-bin count histogram of p over negatives (per-thread shared
//       columns, conflict-free, no atomics in hot loop) + pos stats.
//   K2: exact loss sum for negatives above threshold bin T1, plus a 64-sub-bin
//       count/sum histogram inside bin T1 (shared atomics on ~3% of elements).
//   K3: resolve sub-bin crossing, interpolate partial sub-bin by its measured
//       mean, write scalar, reset globals (graph-replay safe).
// ---------------------------------------------------------------------------

#define NB1 32
#define NB2 64
#define BLK 256
#define GRID_BIG 888   // 148 SMs * 6 CTAs

__device__ unsigned int g_h1[NB1];       // coarse counts of p for negatives
__device__ unsigned int g_h2c[NB2];      // sub-bin counts (inside bin T1)
__device__ float        g_h2s[NB2];      // sub-bin loss sums
__device__ unsigned int g_pos_cnt;
__device__ double       g_pos_sum;
__device__ double       g_above_sum;     // exact loss sum over bins > T1

__device__ __forceinline__ float pos_loss(float p) {
    // -max(log(p), -100)
    return fminf(-__logf(p), 100.0f);
}
__device__ __forceinline__ float neg_loss(float p) {
    // -max(log1p(-p), -100). For p >= 0.5, (1-p) is exact (Sterbenz); for
    // p < 0.5 rounding of (1-p) contributes < 1.3e-7 absolute loss error.
    return fminf(-__logf(1.0f - p), 100.0f);
}

// ---------------------------------------------------------------------------
// K1: coarse histogram + positive stats
// ---------------------------------------------------------------------------
__global__ void __launch_bounds__(BLK) k1_hist(
    const float4* __restrict__ pred4, const float4* __restrict__ gt4,
    const float4* __restrict__ mask4,
    const float* __restrict__ pred, const float* __restrict__ gt,
    const float* __restrict__ mask, int n)
{
    __shared__ unsigned int sh[NB1 * BLK];   // column-major: [bin][tid] -> bank = tid%32
    __shared__ unsigned int binsum[NB1];
    __shared__ unsigned int w_pc[BLK / 32];
    __shared__ float        w_ps[BLK / 32];

    const int tid = threadIdx.x;
#pragma unroll
    for (int b = 0; b < NB1; b++) sh[b * BLK + tid] = 0u;
    if (tid < NB1) binsum[tid] = 0u;
    __syncthreads();

    unsigned int posc = 0;
    float poss = 0.0f;
    const int n4 = n >> 2;

    auto proc = [&](float p, float g, float m) {
        if (m > 0.5f) {
            if (g > 0.5f) {
                posc++;
                poss += pos_loss(p);
            } else {
                int b = (int)(p * 32.0f);
                b = max(0, min(b, NB1 - 1));
                sh[b * BLK + tid] += 1u;   // private column: no conflict, no atomic
            }
        }
    };

    for (int i = blockIdx.x * BLK + tid; i < n4; i += gridDim.x * BLK) {
        float4 p = pred4[i], g = gt4[i], m = mask4[i];
        proc(p.x, g.x, m.x);
        proc(p.y, g.y, m.y);
        proc(p.z, g.z, m.z);
        proc(p.w, g.w, m.w);
    }
    if (blockIdx.x == 0) {
        for (int i = (n4 << 2) + tid; i < n; i += BLK)
            proc(pred[i], gt[i], mask[i]);
    }
    __syncthreads();

    // Flush per-thread columns: 8 threads per bin, staggered (conflict-free).
    {
        const int b  = tid & 31;
        const int j0 = (tid >> 5) * 32;
        unsigned int s = 0;
#pragma unroll
        for (int jj = 0; jj < 32; jj++) {
            int j = j0 + ((jj + b) & 31);
            s += sh[b * BLK + j];
        }
        if (s) atomicAdd(&binsum[b], s);
    }

    // Positive stats: warp reduce -> per-warp slots -> thread 0.
#pragma unroll
    for (int o = 16; o > 0; o >>= 1) {
        posc += __shfl_down_sync(0xffffffffu, posc, o);
        poss += __shfl_down_sync(0xffffffffu, poss, o);
    }
    if ((tid & 31) == 0) { w_pc[tid >> 5] = posc; w_ps[tid >> 5] = poss; }
    __syncthreads();

    if (tid < NB1 && binsum[tid]) atomicAdd(&g_h1[tid], binsum[tid]);
    if (tid == 0) {
        unsigned int pc = 0; float ps = 0.0f;
#pragma unroll
        for (int w = 0; w < BLK / 32; w++) { pc += w_pc[w]; ps += w_ps[w]; }
        if (pc) atomicAdd(&g_pos_cnt, pc);
        atomicAdd(&g_pos_sum, (double)ps);
    }
}

// ---------------------------------------------------------------------------
// K2: exact sum above threshold bin + 64-sub-bin histogram inside it
// ---------------------------------------------------------------------------
__global__ void __launch_bounds__(BLK) k2_refine(
    const float4* __restrict__ pred4, const float4* __restrict__ gt4,
    const float4* __restrict__ mask4,
    const float* __restrict__ pred, const float* __restrict__ gt,
    const float* __restrict__ mask, int n)
{
    __shared__ int          s_T1;
    __shared__ unsigned int s_h1[NB1];
    __shared__ unsigned int s_c2[NB2];
    __shared__ float        s_s2[NB2];
    __shared__ float        w_as[BLK / 32];

    const int tid = threadIdx.x;
    if (tid < NB1) s_h1[tid] = g_h1[tid];
    if (tid < NB2) { s_c2[tid] = 0u; s_s2[tid] = 0.0f; }
    __syncthreads();

    if (tid == 0) {
        long long negtot = 0;
        for (int i = 0; i < NB1; i++) negtot += (long long)s_h1[i];
        unsigned int pos = g_pos_cnt;
        long long k3p = 3LL * (long long)pos;
        long long k = (pos == 0u) ? 0LL : (negtot < k3p ? negtot : k3p);
        int T1 = 1000;  // sentinel: select nothing
        if (k > 0) {
            long long c = 0;
            for (int i = NB1 - 1; i >= 0; i--) {
                c += (long long)s_h1[i];
                if (c >= k) { T1 = i; break; }
            }
        }
        s_T1 = T1;
    }
    __syncthreads();
    const int T1 = s_T1;

    float asum = 0.0f;
    const int n4 = n >> 2;

    auto proc = [&](float p, float g, float m) {
        if (m > 0.5f && g < 0.5f) {
            int b = (int)(p * 32.0f);
            b = max(0, min(b, NB1 - 1));
            if (b >= T1) {
                float loss = neg_loss(p);
                if (b > T1) {
                    asum += loss;
                } else {
                    int b2 = (int)(p * 2048.0f) - T1 * 64;
                    b2 = max(0, min(b2, NB2 - 1));
                    atomicAdd(&s_c2[b2], 1u);
                    atomicAdd(&s_s2[b2], loss);
                }
            }
        }
    };

    for (int i = blockIdx.x * BLK + tid; i < n4; i += gridDim.x * BLK) {
        float4 p = pred4[i], g = gt4[i], m = mask4[i];
        proc(p.x, g.x, m.x);
        proc(p.y, g.y, m.y);
        proc(p.z, g.z, m.z);
        proc(p.w, g.w, m.w);
    }
    if (blockIdx.x == 0) {
        for (int i = (n4 << 2) + tid; i < n; i += BLK)
            proc(pred[i], gt[i], mask[i]);
    }

#pragma unroll
    for (int o = 16; o > 0; o >>= 1)
        asum += __shfl_down_sync(0xffffffffu, asum, o);
    if ((tid & 31) == 0) w_as[tid >> 5] = asum;
    __syncthreads();

    if (tid < NB2 && s_c2[tid]) {
        atomicAdd(&g_h2c[tid], s_c2[tid]);
        atomicAdd(&g_h2s[tid], s_s2[tid]);
    }
    if (tid == 0) {
        float as = 0.0f;
#pragma unroll
        for (int w = 0; w < BLK / 32; w++) as += w_as[w];
        atomicAdd(&g_above_sum, (double)as);
    }
}

// ---------------------------------------------------------------------------
// K3: finalize + reset globals for graph replay
// ---------------------------------------------------------------------------
__global__ void k3_finalize(float* __restrict__ out)
{
    const int tid = threadIdx.x;
    if (tid == 0) {
        long long negtot = 0;
        for (int i = 0; i < NB1; i++) negtot += (long long)g_h1[i];
        unsigned int pos = g_pos_cnt;
        long long k3p = 3LL * (long long)pos;
        long long k = (pos == 0u) ? 0LL : (negtot < k3p ? negtot : k3p);

        double nsum = 0.0;
        if (k > 0) {
            // recompute T1 and count strictly above it
            long long c = 0, cAbove1 = 0;
            int T1 = 0;
            for (int i = NB1 - 1; i >= 0; i--) {
                long long cn = c + (long long)g_h1[i];
                if (cn >= k) { T1 = i; cAbove1 = c; break; }
                c = cn;
            }
            (void)T1;
            long long r = k - cAbove1;  // take r items from bin T1, r >= 1

            long long c2 = 0, cAbove2 = 0;
            double s2above = 0.0;
            int T2 = -1;
            for (int i = NB2 - 1; i >= 0; i--) {
                long long cn = c2 + (long long)g_h2c[i];
                if (cn >= r) { T2 = i; cAbove2 = c2; break; }
                s2above += (double)g_h2s[i];
                c2 = cn;
            }
            double part = 0.0;
            if (T2 >= 0 && g_h2c[T2] > 0u) {
                long long r2 = r - cAbove2;
                if (r2 < 0) r2 = 0;
                part = (double)g_h2s[T2] * ((double)r2 / (double)g_h2c[T2]);
            }
            nsum = g_above_sum + s2above + part;
        }

        double psum  = g_pos_sum;
        double denom = (double)pos + (double)k + 1e-6;
        out[0] = (float)((psum + nsum) / denom);
    }
    __syncthreads();  // all reads done before reset

    if (tid < NB1) g_h1[tid] = 0u;
    for (int i = tid; i < NB2; i += blockDim.x) { g_h2c[i] = 0u; g_h2s[i] = 0.0f; }
    if (tid == 0) {
        g_pos_cnt   = 0u;
        g_pos_sum   = 0.0;
        g_above_sum = 0.0;
    }
}

// ---------------------------------------------------------------------------
extern "C" void kernel_launch(void* const* d_in, const int* in_sizes, int n_in,
                              void* d_out, int out_size)
{
    const float* pred = (const float*)d_in[0];
    const float* gt   = (const float*)d_in[1];
    const float* mask = (const float*)d_in[2];
    float* out = (float*)d_out;
    const int n = in_sizes[0];

    const float4* pred4 = (const float4*)pred;
    const float4* gt4   = (const float4*)gt;
    const float4* mask4 = (const float4*)mask;

    int n4 = n >> 2;
    int grid = (n4 + BLK - 1) / BLK;
    if (grid > GRID_BIG) grid = GRID_BIG;
    if (grid < 1) grid = 1;

    k1_hist<<<grid, BLK>>>(pred4, gt4, mask4, pred, gt, mask, n);
    k2_refine<<<grid, BLK>>>(pred4, gt4, mask4, pred, gt, mask, n);
    k3_finalize<<<1, 128>>>(out);
}